// round 8
// baseline (speedup 1.0000x reference)
#include <cuda_runtime.h>

#define BATCH 16384
#define CH    30
#define GG    49          // 7*7 cells per image
#define CELLS (BATCH * GG) // 802816
#define TPB   256
#define NBLK  ((CELLS + TPB - 1) / TPB)  // 3136

__device__ float g_partials[NBLK];

__global__ void __launch_bounds__(TPB, 3)   // <=84 regs: room for 59 live loads
yolo_cell_kernel(const float* __restrict__ pred, const float* __restrict__ labels) {
    int tid = blockIdx.x * TPB + threadIdx.x;
    float contrib;
    {
        int b    = tid / GG;
        int cell = tid - b * GG;
        int m    = cell / 7;      // dim -2 index -> gx
        int n    = cell - m * 7;  // dim -1 index -> gy

        const float* pb = pred   + (size_t)b * (CH * GG) + cell;
        const float* lb = labels + (size_t)b * (CH * GG) + cell;

        // ---- PHASE 1: issue ALL 59 loads before any arithmetic (max MLP) ----
        float p[30];
        float l[9];
        float lc[20];
        #pragma unroll
        for (int c = 0; c < 10; c++)  p[c] = __ldcs(pb + c * GG);
        #pragma unroll
        for (int c = 10; c < 30; c++) p[c] = __ldcs(pb + c * GG);
        #pragma unroll
        for (int c = 0; c < 9; c++)   l[c] = __ldcs(lb + c * GG);
        #pragma unroll
        for (int c = 0; c < 20; c++)  lc[c] = __ldcs(lb + (10 + c) * GG);

        // ---- PHASE 2: compute ----
        float gx = (float)m, gy = (float)n;
        const float inv = 1.0f / 7.0f;

        // box 1 (pred ch 0..3)
        float cx1 = (p[0] + gx) * inv, cy1 = (p[1] + gy) * inv;
        float a1x1 = cx1 - p[2] * 0.5f, a1y1 = cy1 - p[3] * 0.5f;
        float a1x2 = cx1 + p[2] * 0.5f, a1y2 = cy1 + p[3] * 0.5f;
        // box 2 (pred ch 5..8)
        float cx2 = (p[5] + gx) * inv, cy2 = (p[6] + gy) * inv;
        float a2x1 = cx2 - p[7] * 0.5f, a2y1 = cy2 - p[8] * 0.5f;
        float a2x2 = cx2 + p[7] * 0.5f, a2y2 = cy2 + p[8] * 0.5f;
        // gt box (labels ch 0..3)
        float cxg = (l[0] + gx) * inv, cyg = (l[1] + gy) * inv;
        float bx1 = cxg - l[2] * 0.5f, by1 = cyg - l[3] * 0.5f;
        float bx2 = cxg + l[2] * 0.5f, by2 = cyg + l[3] * 0.5f;

        float areaB = (bx2 - bx1) * (by2 - by1);

        // iou1
        float ix1 = fmaxf(a1x1, bx1), iy1 = fmaxf(a1y1, by1);
        float ix2 = fminf(a1x2, bx2), iy2 = fminf(a1y2, by2);
        float inter1 = fmaxf(ix2 - ix1, 0.0f) * fmaxf(iy2 - iy1, 0.0f);
        float areaA1 = (a1x2 - a1x1) * (a1y2 - a1y1);
        float iou1 = (inter1 > 0.0f) ? inter1 / (areaA1 + areaB - inter1) : 0.0f;

        // iou2
        float jx1 = fmaxf(a2x1, bx1), jy1 = fmaxf(a2y1, by1);
        float jx2 = fminf(a2x2, bx2), jy2 = fminf(a2y2, by2);
        float inter2 = fmaxf(jx2 - jx1, 0.0f) * fmaxf(jy2 - jy1, 0.0f);
        float areaA2 = (a2x2 - a2x1) * (a2y2 - a2y1);
        float iou2 = (inter2 > 0.0f) ? inter2 / (areaA2 + areaB - inter2) : 0.0f;

        bool resp1 = iou1 > iou2;
        float obj = (l[4] == 1.0f) ? 1.0f : 0.0f;

        float d0 = p[0] - l[0], d1 = p[1] - l[1];
        float s2 = sqrtf(p[2]) - sqrtf(l[2]), s3 = sqrtf(p[3]) - sqrtf(l[3]);
        float coor1 = d0*d0 + d1*d1 + s2*s2 + s3*s3;
        float e0 = p[5] - l[5], e1 = p[6] - l[6];
        float t2 = sqrtf(p[7]) - sqrtf(l[7]), t3 = sqrtf(p[8]) - sqrtf(l[8]);
        float coor2 = e0*e0 + e1*e1 + t2*t2 + t3*t3;
        float coor = resp1 ? coor1 : coor2;

        float d4 = p[4] - iou1, d9 = p[9] - iou2;
        float q4 = d4 * d4, q9 = d9 * d9;
        float obj_conf   = resp1 ? q4 : q9;
        float noobj_resp = resp1 ? q9 : q4;

        // class loss: ch 10..29 (operands already in registers)
        float cls = 0.0f;
        #pragma unroll
        for (int c = 0; c < 20; c++) {
            float dc = p[10 + c] - lc[c];
            cls += dc * dc;
        }

        contrib = obj * (5.0f * coor + obj_conf + 0.5f * noobj_resp + cls)
                + (1.0f - obj) * 0.5f * (p[4] * p[4] + p[9] * p[9]);
    }
    double val = (double)contrib;

    // deterministic block reduction (double)
    #pragma unroll
    for (int o = 16; o > 0; o >>= 1)
        val += __shfl_down_sync(0xffffffffu, val, o);

    __shared__ double sdata[TPB / 32];
    int lane = threadIdx.x & 31;
    int wid  = threadIdx.x >> 5;
    if (lane == 0) sdata[wid] = val;
    __syncthreads();
    if (wid == 0) {
        val = (lane < TPB / 32) ? sdata[lane] : 0.0;
        #pragma unroll
        for (int o = 4; o > 0; o >>= 1)
            val += __shfl_down_sync(0xffffffffu, val, o);
        if (lane == 0) g_partials[blockIdx.x] = (float)val;
    }
}

__global__ void __launch_bounds__(256)
yolo_final_kernel(float* __restrict__ out) {
    // 3136 floats = 784 float4; 256 threads x 4 predicated float4 loads
    const float4* p4v = (const float4*)g_partials;
    double val = 0.0;
    #pragma unroll
    for (int k = 0; k < 4; k++) {
        int i = threadIdx.x + k * 256;
        if (i < 784) {
            float4 v = p4v[i];
            val += (double)v.x + (double)v.y + (double)v.z + (double)v.w;
        }
    }

    #pragma unroll
    for (int o = 16; o > 0; o >>= 1)
        val += __shfl_down_sync(0xffffffffu, val, o);

    __shared__ double sdata[8];
    int lane = threadIdx.x & 31;
    int wid  = threadIdx.x >> 5;
    if (lane == 0) sdata[wid] = val;
    __syncthreads();
    if (wid == 0) {
        val = (lane < 8) ? sdata[lane] : 0.0;
        #pragma unroll
        for (int o = 4; o > 0; o >>= 1)
            val += __shfl_down_sync(0xffffffffu, val, o);
        if (lane == 0) out[0] = (float)(val / 6.0);
    }
}

extern "C" void kernel_launch(void* const* d_in, const int* in_sizes, int n_in,
                              void* d_out, int out_size) {
    const float* pred   = (const float*)d_in[0];
    const float* labels = (const float*)d_in[1];
    float* out = (float*)d_out;

    yolo_cell_kernel<<<NBLK, TPB>>>(pred, labels);
    yolo_final_kernel<<<1, 256>>>(out);
}